// round 12
// baseline (speedup 1.0000x reference)
#include <cuda_runtime.h>

// GruAeModel: B=1024, S=1024, F=36, H=20.
// Round 9: all-shuffle operand exchange (no smem x/h round-trips). Broadcast
// operands produced by shfl-from-literal-lane -> candidate for ptxas UR
// promotion (FFMA2 rt 3 -> 2). Single-accumulator chains (no fadd2 folds).

#define HH 20
#define FF 36
#define RR 12
#define BB 1024
#define SS 1024
#define FULLM 0xffffffffu

typedef unsigned long long u64;

__device__ __forceinline__ u64 ffma2(u64 a, u64 b, u64 c) {
    u64 d;
    asm("fma.rn.f32x2 %0, %1, %2, %3;" : "=l"(d) : "l"(a), "l"(b), "l"(c));
    return d;
}
__device__ __forceinline__ float fold2(u64 a) {
    float lo = __uint_as_float((unsigned)a);
    float hi = __uint_as_float((unsigned)(a >> 32));
    return lo + hi;
}
__device__ __forceinline__ u64 pack2(float lo, float hi) {
    u64 d;
    asm("mov.b64 %0, {%1, %2};" : "=l"(d) : "f"(lo), "f"(hi));
    return d;
}
__device__ __forceinline__ float tanha(float x) {
    float y;
    asm("tanh.approx.f32 %0, %1;" : "=f"(y) : "f"(x));
    return y;
}
__device__ __forceinline__ float siga(float x) {
    return fmaf(0.5f, tanha(0.5f * x), 0.5f);
}
__device__ __forceinline__ int imin(int a, int b) { return a < b ? a : b; }

__device__ __forceinline__ void stg_pred(int p, float* addr, float v) {
    asm volatile("{.reg .pred q; setp.ne.s32 q, %0, 0; @q st.global.f32 [%1], %2;}"
                 :: "r"(p), "l"(addr), "f"(v));
}
__device__ __forceinline__ void stg2_pred(int p, float* addr, float v0, float v1) {
    asm volatile("{.reg .pred q; setp.ne.s32 q, %0, 0; @q st.global.v2.f32 [%1], {%2,%3};}"
                 :: "r"(p), "l"(addr), "f"(v0), "f"(v1));
}

// shfl-gather a u64 pair from two literal lanes (warp-uniform result)
#define XPAIR(vlo, vhi, l0, l1) \
    pack2(__shfl_sync(FULLM, (vlo), (l0)), __shfl_sync(FULLM, (vhi), (l1)))

// gate mapping: lane<20: gA=row lane (r), gB=row 20+lane (z)
// lane 20+k (k<10): gA=row 40+k (n lo), gB=row 50+k (n hi); lanes 30,31 junk.

__global__ __launch_bounds__(256, 1) void gruae_fused(
    const float* __restrict__ x, const int* __restrict__ oneh,
    const float* __restrict__ e0t, const float* __restrict__ e1t,
    const float* __restrict__ e2t, const float* __restrict__ e3t,
    const float* __restrict__ Wih1, const float* __restrict__ Whh1,
    const float* __restrict__ bih1, const float* __restrict__ bhh1,
    const float* __restrict__ Wih2, const float* __restrict__ Whh2,
    const float* __restrict__ bih2, const float* __restrict__ bhh2,
    const float* __restrict__ Wfc, const float* __restrict__ bfc,
    float* __restrict__ out) {
    __shared__ __align__(16) float etab[1320];   // e0(40) e1@40 e2@120 e3@520

    const int tid = threadIdx.x;
    const int wid = tid >> 5;
    const int lane = tid & 31;

    for (int i = tid; i < 40; i += 256) etab[i] = e0t[i];
    for (int i = tid; i < 80; i += 256) etab[40 + i] = e1t[i];
    for (int i = tid; i < 400; i += 256) etab[120 + i] = e2t[i];
    for (int i = tid; i < 800; i += 256) etab[520 + i] = e3t[i];

    const int b = blockIdx.x * 8 + wid;

    const int gA = (lane < 20) ? lane : lane + 20;
    const int gB = imin((lane < 20) ? lane + 20 : lane + 30, 59);
    const int nsrc = 20 + (lane % 10);
    const bool nlo = (lane < 10);

    // encoder weights
    u64 wiA[18], wiB[18], whA[10], whB[10];
    {
        const u64* ra = (const u64*)(Wih1 + gA * FF);
        const u64* rb = (const u64*)(Wih1 + gB * FF);
#pragma unroll
        for (int j = 0; j < 18; j++) { wiA[j] = ra[j]; wiB[j] = rb[j]; }
        const u64* ha = (const u64*)(Whh1 + gA * HH);
        const u64* hb = (const u64*)(Whh1 + gB * HH);
#pragma unroll
        for (int j = 0; j < 10; j++) { whA[j] = ha[j]; whB[j] = hb[j]; }
    }
    float biA = bih1[gA], biB = bih1[gB];
    float bhA = bhh1[gA], bhB = bhh1[gB];

    // feature-map constants (branch-free xin build; feature f == lane)
    const int osrcf = (lane < 16) ? 12 : (lane < 20) ? 13 : (lane < 28) ? 14 : 15;
    const int tscale = (lane < 20) ? 4 : 8;
    const int tadd = ((lane < 16) ? (0 - 12) : (lane < 20) ? (40 - 16)
                      : (lane < 28) ? (120 - 20) : (520 - 28)) + lane;

    // unified input stream: lanes<12 raw x cols, 12..15 onehot cols, 16+ dup 15
    const int lc = imin(lane, 15);
    const unsigned* const up = (lc < 12)
        ? (const unsigned*)(x + (size_t)b * SS * RR + lc)
        : (const unsigned*)(oneh + (size_t)b * SS * 4 + (lc - 12));
    const int stride = (lc < 12) ? RR : 4;
    unsigned q0 = up[0], q1 = up[stride], q2 = up[2 * stride];

    float* const origin = out + (size_t)b * SS * FF;
    __syncthreads();

    // build xin(u) per-lane (v = feature lane, v2 = feature 32+(lane&3)),
    // write origin(u), compute gi(u) via shfl-gathered pairs.
    auto build_gi = [&](int u, float& giA_o, float& giB_o) {
        int o = __shfl_sync(FULLM, (int)q0, osrcf);
        int o3 = __shfl_sync(FULLM, (int)q0, 15);
        float ev = etab[tadd + o * tscale];
        float v = (lane < 12) ? __uint_as_float(q0) : ev;
        float v2 = etab[520 + o3 * 8 + 4 + (lane & 3)];
        q0 = q1; q1 = q2;
        q2 = up[(size_t)imin(u + 3, SS - 1) * stride];
        const int inb = (u < SS);
        stg_pred(inb, origin + (size_t)u * FF + lane, v);
        stg_pred(inb && (lane < 4), origin + (size_t)u * FF + 32 + lane, v2);
        u64 ai = pack2(biA, 0.f), bi = pack2(biB, 0.f);
#pragma unroll
        for (int j = 0; j < 16; j++) {
            u64 xk = XPAIR(v, v, 2 * j, 2 * j + 1);
            ai = ffma2(wiA[j], xk, ai);
            bi = ffma2(wiB[j], xk, bi);
        }
        {
            u64 xk = XPAIR(v2, v2, 0, 1);
            ai = ffma2(wiA[16], xk, ai);
            bi = ffma2(wiB[16], xk, bi);
            xk = XPAIR(v2, v2, 2, 3);
            ai = ffma2(wiA[17], xk, ai);
            bi = ffma2(wiB[17], xk, bi);
        }
        giA_o = fold2(ai);
        giB_o = fold2(bi);
    };

    float giA0, giB0, giA1, giB1;
    build_gi(0, giA0, giB0);
    build_gi(1, giA1, giB1);

    float hreg = 0.f;
    // ================= encoder (gi pipelined +2; h exchanged by shfl) ======
    for (int t = 0; t < SS; t++) {
        float giA2, giB2;
        build_gi(t + 2, giA2, giB2);
        u64 ah = pack2(bhA, 0.f), bh = pack2(bhB, 0.f);
#pragma unroll
        for (int j = 0; j < 10; j++) {
            u64 hk = XPAIR(hreg, hreg, 2 * j, 2 * j + 1);
            ah = ffma2(whA[j], hk, ah);
            bh = ffma2(whB[j], hk, bh);
        }
        float ghA = fold2(ah);
        float ghB = fold2(bh);
        float s_iA = __shfl_sync(FULLM, giA0, nsrc);
        float s_iB = __shfl_sync(FULLM, giB0, nsrc);
        float s_hA = __shfl_sync(FULLM, ghA, nsrc);
        float s_hB = __shfl_sync(FULLM, ghB, nsrc);
        float in = nlo ? s_iA : s_iB;
        float hn = nlo ? s_hA : s_hB;
        float r = siga(giA0 + ghA);
        float z = siga(giB0 + ghB);
        float n = tanha(fmaf(r, hn, in));
        hreg = fmaf(z, hreg - n, n);
        giA0 = giA1; giB0 = giB1; giA1 = giA2; giB1 = giB2;
    }

    // ---- handoff + decoder weights ----
    hreg = tanha(hreg);
    {
        const u64* ra = (const u64*)(Wih2 + gA * FF);
        const u64* rb = (const u64*)(Wih2 + gB * FF);
#pragma unroll
        for (int j = 0; j < 18; j++) { wiA[j] = ra[j]; wiB[j] = rb[j]; }
        const u64* ha = (const u64*)(Whh2 + gA * HH);
        const u64* hb = (const u64*)(Whh2 + gB * HH);
#pragma unroll
        for (int j = 0; j < 10; j++) { whA[j] = ha[j]; whB[j] = hb[j]; }
    }
    biA = bih2[gA]; biB = bih2[gB];
    bhA = bhh2[gA]; bhB = bhh2[gB];
    u64 wf0[10], wf1[10];
    const int fr0 = (lane < 18) ? 2 * lane : 0;
    const int fr1 = (lane < 18) ? 2 * lane + 1 : 0;
    {
        const u64* f0 = (const u64*)(Wfc + fr0 * HH);
        const u64* f1 = (const u64*)(Wfc + fr1 * HH);
#pragma unroll
        for (int j = 0; j < 10; j++) { wf0[j] = f0[j]; wf1[j] = f1[j]; }
    }
    const float bf0 = bfc[fr0], bf1 = bfc[fr1];
    float* const xsout = out + (size_t)(BB + b) * SS * FF;
    const int predX = (lane < 18);

    // t=0: FC -> (v0,v1) pair 'lane'; gh matvec carried. h pairs via shfl.
    float v0, v1, ghAc, ghBc;
    {
        u64 f0 = pack2(bf0, 0.f), f1 = pack2(bf1, 0.f);
        u64 ah = pack2(bhA, 0.f), ch = pack2(bhB, 0.f);
#pragma unroll
        for (int j = 0; j < 10; j++) {
            u64 hk = XPAIR(hreg, hreg, 2 * j, 2 * j + 1);
            f0 = ffma2(wf0[j], hk, f0);
            f1 = ffma2(wf1[j], hk, f1);
            ah = ffma2(whA[j], hk, ah);
            ch = ffma2(whB[j], hk, ch);
        }
        v0 = tanha(fold2(f0));
        v1 = tanha(fold2(f1));
        stg2_pred(predX, xsout + (size_t)(SS - 1) * FF + 2 * lane, v0, v1);
        ghAc = fold2(ah);
        ghBc = fold2(ch);
    }

    // ================= decoder (all-shuffle exchange) =================
    for (int t = 1; t < SS; t++) {
        // gi from (v0,v1): x pair j lives in lane j (j<18)
        u64 ai = pack2(biA, 0.f), bi = pack2(biB, 0.f);
#pragma unroll
        for (int j = 0; j < 18; j++) {
            u64 xk = XPAIR(v0, v1, j, j);
            ai = ffma2(wiA[j], xk, ai);
            bi = ffma2(wiB[j], xk, bi);
        }
        float giA = fold2(ai);
        float giB = fold2(bi);
        float s_iA = __shfl_sync(FULLM, giA, nsrc);
        float s_iB = __shfl_sync(FULLM, giB, nsrc);
        float s_hA = __shfl_sync(FULLM, ghAc, nsrc);
        float s_hB = __shfl_sync(FULLM, ghBc, nsrc);
        float in = nlo ? s_iA : s_iB;
        float hn = nlo ? s_hA : s_hB;
        float r = siga(giA + ghAc);
        float z = siga(giB + ghBc);
        float n = tanha(fmaf(r, hn, in));
        hreg = tanha(fmaf(z, hreg - n, n));
        // FC (this step) + gh (next step) from new h, pairs via shfl
        u64 f0 = pack2(bf0, 0.f), f1 = pack2(bf1, 0.f);
        u64 ah = pack2(bhA, 0.f), ch = pack2(bhB, 0.f);
#pragma unroll
        for (int j = 0; j < 10; j++) {
            u64 hk = XPAIR(hreg, hreg, 2 * j, 2 * j + 1);
            f0 = ffma2(wf0[j], hk, f0);
            f1 = ffma2(wf1[j], hk, f1);
            ah = ffma2(whA[j], hk, ah);
            ch = ffma2(whB[j], hk, ch);
        }
        v0 = tanha(fold2(f0));
        v1 = tanha(fold2(f1));
        stg2_pred(predX, xsout + (size_t)(SS - 1 - t) * FF + 2 * lane, v0, v1);
        ghAc = fold2(ah);
        ghBc = fold2(ch);
    }
}

extern "C" void kernel_launch(void* const* d_in, const int* in_sizes, int n_in,
                              void* d_out, int out_size) {
    const float* x    = (const float*)d_in[0];
    const int*   oneh = (const int*)d_in[1];
    const float* e0   = (const float*)d_in[2];
    const float* e1   = (const float*)d_in[3];
    const float* e2   = (const float*)d_in[4];
    const float* e3   = (const float*)d_in[5];
    const float* Wih1 = (const float*)d_in[6];
    const float* Whh1 = (const float*)d_in[7];
    const float* bih1 = (const float*)d_in[8];
    const float* bhh1 = (const float*)d_in[9];
    const float* Wih2 = (const float*)d_in[10];
    const float* Whh2 = (const float*)d_in[11];
    const float* bih2 = (const float*)d_in[12];
    const float* bhh2 = (const float*)d_in[13];
    const float* Wfc  = (const float*)d_in[14];
    const float* bfc  = (const float*)d_in[15];

    gruae_fused<<<BB / 8, 256>>>(
        x, oneh, e0, e1, e2, e3, Wih1, Whh1, bih1, bhh1,
        Wih2, Whh2, bih2, bhh2, Wfc, bfc, (float*)d_out);
}